// round 8
// baseline (speedup 1.0000x reference)
#include <cuda_runtime.h>
#include <cuda_fp16.h>

#define FN 128
#define FE 64
#define KN 32
#define NMAX 50000

// Scratch (static device arrays — the sanctioned workaround)
__device__ float  g_wqk[FN * FE];           // [128][64] = wq @ wk^T
__device__ float  g_qk[NMAX * FE];          // [N][64]
__device__ __half g_nodesVh[NMAX * FN];     // [N][128] fp16 V rows

typedef unsigned long long ull;

__device__ __forceinline__ void fma2(ull& d, ull a, ull b) {
    asm("fma.rn.f32x2 %0, %1, %2, %0;" : "+l"(d) : "l"(a), "l"(b));
}
__device__ __forceinline__ ull pack2(float x, float y) {
    ull r; asm("mov.b64 %0, {%1, %2};" : "=l"(r) : "f"(x), "f"(y)); return r;
}
__device__ __forceinline__ void unpack2(float& x, float& y, ull v) {
    asm("mov.b64 {%0, %1}, %2;" : "=f"(x), "=f"(y) : "l"(v));
}

// ---------------------------------------------------------------------------
// K0: wqk[f][j] = sum_t wq[f][t] * wk[j][t]   (8192 outputs, dot-64 each)
// ---------------------------------------------------------------------------
__global__ void k0_weights(const float* __restrict__ wq,
                           const float* __restrict__ wk) {
    int idx = blockIdx.x * blockDim.x + threadIdx.x;   // 0..8191
    int f = idx >> 6, j = idx & 63;
    float acc = 0.f;
    #pragma unroll 8
    for (int t = 0; t < FE; t++) acc += wq[f * FE + t] * wk[j * FE + t];
    g_wqk[idx] = acc;
}

// ---------------------------------------------------------------------------
// K1: C[N,192] = nodes[N,128] @ [wqk | wv]. Tile 128 rows x 64 cols per block,
// 256 threads, 8 rows x 4 cols per thread, packed f32x2 FMA (row pairs).
// panel 0 -> g_qk (fp32), panels 1,2 -> g_nodesVh (fp16).
// ---------------------------------------------------------------------------
__global__ __launch_bounds__(256) void k1_gemm(const float* __restrict__ nodes,
                                               const float* __restrict__ wv,
                                               int N) {
    extern __shared__ float sm[];
    float* As = sm;                // [128 k][128 row]  (transposed!)  64KB
    float* Bs = sm + 128 * 128;    // [128 k][64 col]                 32KB

    int tid   = threadIdx.x;
    int row0  = blockIdx.x * 128;
    int panel = blockIdx.y;        // 0: qk, 1: V[0:64], 2: V[64:128]

    // ---- Load A tile transposed: As[k][row]. L1 absorbs the strided reads.
    const float4* nodes4 = (const float4*)nodes;
    #pragma unroll
    for (int c = 0; c < 16; c++) {
        int idx = c * 256 + tid;           // 0..4095
        int row = idx & 127;
        int k4  = idx >> 7;                // 0..31
        int grow = row0 + row;
        float4 v = (grow < N) ? nodes4[(size_t)grow * 32 + k4]
                              : make_float4(0.f, 0.f, 0.f, 0.f);
        As[(k4 * 4 + 0) * 128 + row] = v.x;
        As[(k4 * 4 + 1) * 128 + row] = v.y;
        As[(k4 * 4 + 2) * 128 + row] = v.z;
        As[(k4 * 4 + 3) * 128 + row] = v.w;
    }
    // ---- Load B panel [128 k][64 cols]
    if (panel == 0) {
        const float4* B4 = (const float4*)g_wqk;           // row stride 16
        #pragma unroll
        for (int c = 0; c < 8; c++) {
            int idx = c * 256 + tid;
            int k = idx >> 4, j4 = idx & 15;
            ((float4*)(Bs + k * 64))[j4] = B4[k * 16 + j4];
        }
    } else {
        const float4* B4 = (const float4*)wv;              // row stride 32
        int off = (panel - 1) * 16;
        #pragma unroll
        for (int c = 0; c < 8; c++) {
            int idx = c * 256 + tid;
            int k = idx >> 4, j4 = idx & 15;
            ((float4*)(Bs + k * 64))[j4] = B4[k * 32 + off + j4];
        }
    }
    __syncthreads();

    int tx = tid & 15;             // col group (x4)
    int ty = tid >> 4;             // row group (x8), as 4 row-pairs
    ull acc[4][4];                 // [rowpair][col], (0.f,0.f) == 0ull
    #pragma unroll
    for (int p = 0; p < 4; p++)
        #pragma unroll
        for (int c = 0; c < 4; c++) acc[p][c] = 0ull;

    #pragma unroll 8
    for (int k = 0; k < 128; k++) {
        const ull* ap = (const ull*)(As + k * 128 + ty * 8);  // 4 row pairs
        ull a0 = ap[0], a1 = ap[1], a2 = ap[2], a3 = ap[3];
        float4 b = ((const float4*)(Bs + k * 64))[tx];
        ull b0 = pack2(b.x, b.x), b1 = pack2(b.y, b.y);
        ull b2 = pack2(b.z, b.z), b3 = pack2(b.w, b.w);
        fma2(acc[0][0], a0, b0); fma2(acc[0][1], a0, b1); fma2(acc[0][2], a0, b2); fma2(acc[0][3], a0, b3);
        fma2(acc[1][0], a1, b0); fma2(acc[1][1], a1, b1); fma2(acc[1][2], a1, b2); fma2(acc[1][3], a1, b3);
        fma2(acc[2][0], a2, b0); fma2(acc[2][1], a2, b1); fma2(acc[2][2], a2, b2); fma2(acc[2][3], a2, b3);
        fma2(acc[3][0], a3, b0); fma2(acc[3][1], a3, b1); fma2(acc[3][2], a3, b2); fma2(acc[3][3], a3, b3);
    }

    // ---- Epilogue
    #pragma unroll
    for (int p = 0; p < 4; p++) {
        float lo[4], hi[4];
        #pragma unroll
        for (int c = 0; c < 4; c++) unpack2(lo[c], hi[c], acc[p][c]);
        int g0 = row0 + ty * 8 + 2 * p;
        int g1 = g0 + 1;
        if (panel == 0) {
            if (g0 < N) ((float4*)g_qk)[(size_t)g0 * 16 + tx] = make_float4(lo[0], lo[1], lo[2], lo[3]);
            if (g1 < N) ((float4*)g_qk)[(size_t)g1 * 16 + tx] = make_float4(hi[0], hi[1], hi[2], hi[3]);
        } else {
            int cb = (panel - 1) * 64 + tx * 4;
            if (g0 < N) {
                __half2* vh = (__half2*)(g_nodesVh + (size_t)g0 * 128 + cb);
                vh[0] = __floats2half2_rn(lo[0], lo[1]);
                vh[1] = __floats2half2_rn(lo[2], lo[3]);
            }
            if (g1 < N) {
                __half2* vh = (__half2*)(g_nodesVh + (size_t)g1 * 128 + cb);
                vh[0] = __floats2half2_rn(hi[0], hi[1]);
                vh[1] = __floats2half2_rn(hi[2], hi[3]);
            }
        }
    }
}

// ---------------------------------------------------------------------------
// K2: 2 nodes per 128-thread block; 64 lanes per node.
// Per node: logits = inv_deg * edges[n].qk[n], softmax(K=32),
// out[n] = sum_k b[k] * nodesVh[nlist[n,k]] via __half2 gathers (fp32 accum).
// ---------------------------------------------------------------------------
__global__ __launch_bounds__(128) void k2_fused(const float* __restrict__ edges,
                                                const int*   __restrict__ nlist,
                                                const float* __restrict__ invdeg,
                                                float*       __restrict__ out,
                                                int N) {
    int tid = threadIdx.x;
    int h   = tid >> 6;                    // 0/1: which node in this block
    int lt  = tid & 63;                    // lane within the node
    int n   = blockIdx.x * 2 + h;
    bool live = (n < N);
    int nc = live ? n : (N - 1);           // clamped index for safe loads

    __shared__ __align__(16) float qk_s[2][64];
    __shared__ float logits[2][32];
    __shared__ float b_s[2][32];
    __shared__ int   idx_s[2][32];

    qk_s[h][lt] = g_qk[(size_t)nc * 64 + lt];
    if (lt < 32) idx_s[h][lt] = nlist[(size_t)nc * KN + lt];
    __syncthreads();

    // ---- logits: 2 threads per k, each does half the dot-64 (8 float4s)
    int k    = lt >> 1;
    int part = lt & 1;
    const float4* e4 = (const float4*)edges + (size_t)nc * 512 + k * 16 + part * 8;
    const float4* q4 = (const float4*)qk_s[h] + part * 8;

    float s = 0.f;
    #pragma unroll
    for (int i = 0; i < 8; i++) {
        float4 v = e4[i], q = q4[i];
        s += v.x * q.x + v.y * q.y + v.z * q.z + v.w * q.w;
    }
    s += __shfl_xor_sync(0xffffffffu, s, 1);
    if (part == 0) logits[h][k] = s;
    __syncthreads();

    // ---- softmax over 32: warp 0 (node 0) and warp 2 (node 1)
    if (lt < 32) {
        float v = logits[h][lt] * invdeg[nc];
        float m = v;
        #pragma unroll
        for (int o = 16; o; o >>= 1) m = fmaxf(m, __shfl_xor_sync(0xffffffffu, m, o));
        float e = __expf(v - m);
        float sum = e;
        #pragma unroll
        for (int o = 16; o; o >>= 1) sum += __shfl_xor_sync(0xffffffffu, sum, o);
        b_s[h][lt] = e / sum;
    }
    __syncthreads();

    // ---- weighted __half2 gather (full 128B line per warp per row)
    const __half2* vh = (const __half2*)g_nodesVh;      // row stride 64 half2
    float accx = 0.f, accy = 0.f;
    #pragma unroll
    for (int kk = 0; kk < KN; kk++) {
        float  bw = b_s[h][kk];
        float2 v  = __half22float2(vh[(size_t)idx_s[h][kk] * 64 + lt]);
        accx += bw * v.x;
        accy += bw * v.y;
    }
    if (live) ((float2*)out)[(size_t)n * 64 + lt] = make_float2(accx, accy);
}

// ---------------------------------------------------------------------------
extern "C" void kernel_launch(void* const* d_in, const int* in_sizes, int n_in,
                              void* d_out, int out_size) {
    const float* nodes  = (const float*)d_in[0];
    const int*   nlist  = (const int*)  d_in[1];
    const float* edges  = (const float*)d_in[2];
    const float* invdeg = (const float*)d_in[3];
    const float* wq     = (const float*)d_in[4];
    const float* wk     = (const float*)d_in[5];
    const float* wv     = (const float*)d_in[6];
    float* out = (float*)d_out;
    int N = in_sizes[3];                           // inv_degree element count

    const int smem1 = (128 * 128 + 128 * 64) * 4;  // 96 KB
    cudaFuncSetAttribute(k1_gemm, cudaFuncAttributeMaxDynamicSharedMemorySize, smem1);

    k0_weights<<<32, 256>>>(wq, wk);
    dim3 g1((N + 127) / 128, 3);
    k1_gemm<<<g1, 256, smem1>>>(nodes, wv, N);
    k2_fused<<<(N + 1) / 2, 128>>>(edges, nlist, invdeg, out, N);
}